// round 9
// baseline (speedup 1.0000x reference)
#include <cuda_runtime.h>
#include <cstdint>

// Pooling_83141976916902: degenerate softmax gate => pure sorted segment-sum.
//   out[g, :] = sum_{n : batch[n]==g} x[n, :],  N=1e6, C=128.
//
// R9 = R6 main loop (cp.async.cg double-buffer, 5 blocks/SM, best kernel
// 85.8us @ DRAM 78.3% = measured pattern ceiling) + FUSED output zeroing:
//  - each block issues its prologue cp.asyncs first (reads in flight),
//  - zeroes its slice of out (overlapped with DRAM latency),
//  - device-wide arrive/spin barrier before the FIRST atomic flush only.
// Removes the separate zero kernel + its launch serialization (~0.7-1.9us).
// Single wave (740 blocks, 5/SM) => spin cannot deadlock. Counters are
// reset by the last block each launch => identical behavior every replay.

#define CCH 128
#define WPB 4            // warps per block (128 threads)
#define RPS 8            // rows per stage (8 x 512B = 4KB per warp-stage)
#define NBLK (148 * 5)   // single wave, 5 blocks/SM (33.8KB smem each)

__device__ unsigned int g_zero_arrive = 0;
__device__ unsigned int g_done_ctr    = 0;

__device__ __forceinline__ int seg_at(const void* batch, int n, bool is64) {
    if (is64) return (int)__ldg(((const long long*)batch) + n);
    return __ldg(((const int*)batch) + n);
}

__device__ __forceinline__ void red_add_v4(float* addr, float4 v) {
    asm volatile("red.global.add.v4.f32 [%0], {%1, %2, %3, %4};"
                 :: "l"(addr), "f"(v.x), "f"(v.y), "f"(v.z), "f"(v.w)
                 : "memory");
}

__device__ __forceinline__ void cp16(unsigned int saddr, const void* gptr) {
    asm volatile("cp.async.cg.shared.global [%0], [%1], 16;"
                 :: "r"(saddr), "l"(gptr));
}
__device__ __forceinline__ void cp_commit() {
    asm volatile("cp.async.commit_group;" ::: "memory");
}
template <int NREM>
__device__ __forceinline__ void cp_wait() {
    asm volatile("cp.async.wait_group %0;" :: "n"(NREM) : "memory");
}

__global__ __launch_bounds__(WPB * 32) void seg_sum_kernel(
    const float4* __restrict__ x4,     // N rows x 32 float4
    const void*   __restrict__ batch,  // int32 or int64, sorted
    float*        __restrict__ out,    // [G * 128]
    int N, int out_n4, int nwarp_total)
{
    __shared__ float4 buf[WPB][2][RPS][32];   // 32KB

    // dtype probe: odd int32 index mid-array. int64 -> high word == 0;
    // int32 -> sorted mid segment id != 0. In-bounds either way.
    const int probe = ((N >> 1) | 1);
    const bool is64 = (__ldg(((const int*)batch) + probe) == 0);

    const int gwarp = (blockIdx.x * blockDim.x + threadIdx.x) >> 5;
    const int warp  = threadIdx.x >> 5;
    const int lane  = threadIdx.x & 31;

    const int chunk = (N + nwarp_total - 1) / nwarp_total;
    int n0 = gwarp * chunk;
    int n1 = n0 + chunk;
    if (n1 > N) n1 = N;
    const bool has_work = (n0 < n1);

    const float4* gp = x4 + n0 * 32 + lane;   // this lane's column, row n0
    const int rows = has_work ? (n1 - n0) : 0;
    const int T = rows & ~(RPS - 1);          // full-stage rows

    unsigned int sb[2];
    sb[0] = (unsigned int)__cvta_generic_to_shared(&buf[warp][0][0][lane]);
    sb[1] = (unsigned int)__cvta_generic_to_shared(&buf[warp][1][0][lane]);

    // ---- 1) prologue: get DRAM reads in flight immediately ----
    int issued = 0;
    #pragma unroll
    for (int s = 0; s < 2; s++) {
        if (issued + RPS <= T) {
            #pragma unroll
            for (int r = 0; r < RPS; r++)
                cp16(sb[s] + r * 512, gp + (issued + r) * 32);
            cp_commit();
            issued += RPS;
        }
    }

    // ---- 2) zero my slice of out (overlaps with in-flight reads) ----
    {
        float4* o4 = (float4*)out;
        for (int i = blockIdx.x * blockDim.x + threadIdx.x; i < out_n4;
             i += NBLK * WPB * 32)
            o4[i] = make_float4(0.f, 0.f, 0.f, 0.f);
    }
    __threadfence();
    __syncthreads();
    if (threadIdx.x == 0) atomicAdd(&g_zero_arrive, 1u);

    // ---- 3) wait for ALL blocks' zeroing before the first flush ----
    // (single wave => every block is resident => no deadlock)
    while (*(volatile unsigned int*)&g_zero_arrive < (unsigned int)NBLK)
        __nanosleep(64);

    if (has_work) {
        float4 acc = make_float4(0.f, 0.f, 0.f, 0.f);
        int cur = seg_at(batch, n0, is64);

        for (int t = 0; t < T; t += RPS) {
            const int stg = (t / RPS) & 1;
            if (issued - t > RPS) cp_wait<1>();   // 2 groups out: wait oldest
            else                  cp_wait<0>();   // last group: wait all

            int s[RPS];
            #pragma unroll
            for (int r = 0; r < RPS; r++)
                s[r] = seg_at(batch, n0 + t + r, is64);   // L1 broadcast hits

            #pragma unroll
            for (int r = 0; r < RPS; r++) {
                float4 v = buf[warp][stg][r][lane];
                if (s[r] != cur) {
                    red_add_v4(out + cur * CCH + lane * 4, acc);
                    acc = make_float4(0.f, 0.f, 0.f, 0.f);
                    cur = s[r];
                }
                acc.x += v.x; acc.y += v.y; acc.z += v.z; acc.w += v.w;
            }

            if (issued + RPS <= T) {              // refill the freed buffer
                #pragma unroll
                for (int r = 0; r < RPS; r++)
                    cp16(sb[stg] + r * 512, gp + (issued + r) * 32);
                cp_commit();
                issued += RPS;
            }
        }

        for (int n = n0 + T; n < n1; n++) {       // tail rows
            float4 v = __ldg(gp + (n - n0) * 32);
            int s = seg_at(batch, n, is64);
            if (s != cur) {
                red_add_v4(out + cur * CCH + lane * 4, acc);
                acc = make_float4(0.f, 0.f, 0.f, 0.f);
                cur = s;
            }
            acc.x += v.x; acc.y += v.y; acc.z += v.z; acc.w += v.w;
        }
        red_add_v4(out + cur * CCH + lane * 4, acc);
    }

    // ---- 4) reset barrier counters for the next (graph-replayed) launch ----
    __syncthreads();
    if (threadIdx.x == 0) {
        unsigned int old = atomicAdd(&g_done_ctr, 1u);
        if (old == (unsigned int)NBLK - 1u) {     // last block out resets
            g_zero_arrive = 0u;
            g_done_ctr    = 0u;
            __threadfence();
        }
    }
}

extern "C" void kernel_launch(void* const* d_in, const int* in_sizes, int n_in,
                              void* d_out, int out_size) {
    const float* x     = (const float*)d_in[0];   // [N, 128] fp32
    const void*  batch = d_in[1];                 // [N] int32/int64 sorted
    float* out = (float*)d_out;

    const int N = in_sizes[1];
    const int nwarps = NBLK * WPB;

    seg_sum_kernel<<<NBLK, WPB * 32>>>((const float4*)x, batch, out,
                                       N, out_size / 4, nwarps);
}

// round 10
// speedup vs baseline: 1.0662x; 1.0662x over previous
#include <cuda_runtime.h>
#include <cstdint>

// Pooling_83141976916902: degenerate softmax gate => pure sorted segment-sum.
//   out[g, :] = sum_{n : batch[n]==g} x[n, :],  N=1e6, C=128.
//
// R10 = R6 (best: 86.5us total, kernel 85.8us @ DRAM 78.3% = measured
// pattern ceiling across R1/R4/R6/R8) with the zero kernel replaced by a
// cudaMemsetAsync (graph memset node; value 0x00 == 0.0f).
// R9 lesson: a device-wide spin barrier to fuse the zeroing costs ~9.5us
// of kernel time to save 0.7us of launch -- never again for sub-us wins.

#define CCH 128
#define WPB 4            // warps per block (128 threads)
#define RPS 8            // rows per stage (8 x 512B = 4KB per warp-stage)

__device__ __forceinline__ int seg_at(const void* batch, int n, bool is64) {
    if (is64) return (int)__ldg(((const long long*)batch) + n);
    return __ldg(((const int*)batch) + n);
}

__device__ __forceinline__ void red_add_v4(float* addr, float4 v) {
    asm volatile("red.global.add.v4.f32 [%0], {%1, %2, %3, %4};"
                 :: "l"(addr), "f"(v.x), "f"(v.y), "f"(v.z), "f"(v.w)
                 : "memory");
}

__device__ __forceinline__ void cp16(unsigned int saddr, const void* gptr) {
    asm volatile("cp.async.cg.shared.global [%0], [%1], 16;"
                 :: "r"(saddr), "l"(gptr));
}
__device__ __forceinline__ void cp_commit() {
    asm volatile("cp.async.commit_group;" ::: "memory");
}
template <int NREM>
__device__ __forceinline__ void cp_wait() {
    asm volatile("cp.async.wait_group %0;" :: "n"(NREM) : "memory");
}

__global__ __launch_bounds__(WPB * 32) void seg_sum_kernel(
    const float4* __restrict__ x4,     // N rows x 32 float4
    const void*   __restrict__ batch,  // int32 or int64, sorted
    float*        __restrict__ out,    // [G * 128]
    int N, int nwarp_total)
{
    __shared__ float4 buf[WPB][2][RPS][32];   // 32KB

    // dtype probe: odd int32 index mid-array. int64 -> high word == 0;
    // int32 -> sorted mid segment id != 0. In-bounds either way.
    const int probe = ((N >> 1) | 1);
    const bool is64 = (__ldg(((const int*)batch) + probe) == 0);

    const int gwarp = (blockIdx.x * blockDim.x + threadIdx.x) >> 5;
    const int warp  = threadIdx.x >> 5;
    const int lane  = threadIdx.x & 31;

    const int chunk = (N + nwarp_total - 1) / nwarp_total;
    int n0 = gwarp * chunk;
    int n1 = n0 + chunk;
    if (n1 > N) n1 = N;
    if (n0 >= n1) return;

    float4 acc = make_float4(0.f, 0.f, 0.f, 0.f);
    int cur = seg_at(batch, n0, is64);

    const float4* gp = x4 + n0 * 32 + lane;   // this lane's column, row n0
    const int rows = n1 - n0;
    const int T = rows & ~(RPS - 1);          // full-stage rows

    unsigned int sb[2];
    sb[0] = (unsigned int)__cvta_generic_to_shared(&buf[warp][0][0][lane]);
    sb[1] = (unsigned int)__cvta_generic_to_shared(&buf[warp][1][0][lane]);

    int issued = 0;
    #pragma unroll
    for (int s = 0; s < 2; s++) {
        if (issued + RPS <= T) {
            #pragma unroll
            for (int r = 0; r < RPS; r++)
                cp16(sb[s] + r * 512, gp + (issued + r) * 32);
            cp_commit();
            issued += RPS;
        }
    }

    for (int t = 0; t < T; t += RPS) {
        const int stg = (t / RPS) & 1;
        if (issued - t > RPS) cp_wait<1>();   // 2 groups out: wait oldest
        else                  cp_wait<0>();   // last group: wait all

        int s[RPS];
        #pragma unroll
        for (int r = 0; r < RPS; r++)
            s[r] = seg_at(batch, n0 + t + r, is64);   // L1 broadcast hits

        #pragma unroll
        for (int r = 0; r < RPS; r++) {
            float4 v = buf[warp][stg][r][lane];
            if (s[r] != cur) {
                red_add_v4(out + cur * CCH + lane * 4, acc);
                acc = make_float4(0.f, 0.f, 0.f, 0.f);
                cur = s[r];
            }
            acc.x += v.x; acc.y += v.y; acc.z += v.z; acc.w += v.w;
        }

        if (issued + RPS <= T) {              // refill the freed buffer
            #pragma unroll
            for (int r = 0; r < RPS; r++)
                cp16(sb[stg] + r * 512, gp + (issued + r) * 32);
            cp_commit();
            issued += RPS;
        }
    }

    for (int n = n0 + T; n < n1; n++) {       // tail rows
        float4 v = __ldg(gp + (n - n0) * 32);
        int s = seg_at(batch, n, is64);
        if (s != cur) {
            red_add_v4(out + cur * CCH + lane * 4, acc);
            acc = make_float4(0.f, 0.f, 0.f, 0.f);
            cur = s;
        }
        acc.x += v.x; acc.y += v.y; acc.z += v.z; acc.w += v.w;
    }
    red_add_v4(out + cur * CCH + lane * 4, acc);
}

extern "C" void kernel_launch(void* const* d_in, const int* in_sizes, int n_in,
                              void* d_out, int out_size) {
    const float* x     = (const float*)d_in[0];   // [N, 128] fp32
    const void*  batch = d_in[1];                 // [N] int32/int64 sorted
    float* out = (float*)d_out;

    const int N = in_sizes[1];

    // zero the output via a graph memset node (0x00 bytes == 0.0f)
    cudaMemsetAsync(out, 0, (size_t)out_size * sizeof(float));

    const int blocks = 148 * 5;                   // single wave, 5 blocks/SM
    const int nwarps = blocks * WPB;
    seg_sum_kernel<<<blocks, WPB * 32>>>((const float4*)x, batch, out, N, nwarps);
}